// round 6
// baseline (speedup 1.0000x reference)
#include <cuda_runtime.h>
#include <cstdint>

// ---------------------------------------------------------------------------
// D_MPNNLayer on GB300 (sm_103a via compute_103 -> mma.sync tf32)
// Dst-sorted edge processing (register accumulation of segment sums) +
// src-CSR LayerNorm (per-node stats, per-edge write only).
// ---------------------------------------------------------------------------

constexpr int NN = 40000;
constexpr int NE = 640000;

constexpr int LDT = 132;
constexpr int TW = 128 * LDT;
constexpr int EDGE_SMEM = (3 * TW) * 4 + 2048;
constexpr int XAB_SMEM = (2 * TW) * 4;

__device__ float g_xab[(size_t)NN * 256];
__device__ float g_mnode[(size_t)NN * 128];
__device__ float g_p[(size_t)NN * 128];

__device__ int g_histD[NN], g_histS[NN];
__device__ int g_workD[NN], g_workS[NN];
__device__ int g_startD[NN + 8], g_startS[NN + 8];
__device__ int g_permD[NE], g_permS[NE];
__device__ int g_sdstD[NE], g_ssrcD[NE];

__device__ __host__ __forceinline__ int permL(int r) {
    return (r & 0x61) | ((r >> 2) & 0x02) | ((r & 0x06) << 1) | (r & 0x10);
}

// ---------------- helpers ----------------------------------------------------
__device__ __forceinline__ uint32_t smem_u32(const void* p) {
    uint32_t a;
    asm("{ .reg .u64 t; cvta.to.shared.u64 t, %1; cvt.u32.u64 %0, t; }" : "=r"(a) : "l"(p));
    return a;
}
__device__ __forceinline__ uint32_t cvt_tf32(float f) {
    uint32_t r;
    asm("cvt.rna.tf32.f32 %0, %1;" : "=r"(r) : "f"(f));
    return r;
}
__device__ __forceinline__ void cpa16(uint32_t s, const void* g) {
    asm volatile("cp.async.cg.shared.global [%0], [%1], 16;" ::"r"(s), "l"(g));
}
__device__ __forceinline__ void cpa_commit() {
    asm volatile("cp.async.commit_group;" ::: "memory");
}
__device__ __forceinline__ void mma8(float acc[4], uint32_t a0, uint32_t a1, uint32_t a2,
                                     uint32_t a3, uint32_t b0, uint32_t b1) {
    asm("mma.sync.aligned.m16n8k8.row.col.f32.tf32.tf32.f32 "
        "{%0,%1,%2,%3}, {%4,%5,%6,%7}, {%8,%9}, {%0,%1,%2,%3};"
        : "+f"(acc[0]), "+f"(acc[1]), "+f"(acc[2]), "+f"(acc[3])
        : "r"(a0), "r"(a1), "r"(a2), "r"(a3), "r"(b0), "r"(b1));
}
__device__ __forceinline__ void redv4(float* p, float4 v) {
    asm volatile("red.global.add.v4.f32 [%0], {%1,%2,%3,%4};" ::"l"(p), "f"(v.x), "f"(v.y),
                 "f"(v.z), "f"(v.w)
                 : "memory");
}

// Stage 128x128 fp32 -> tf32(rna), optional row permutation (weights).
template <int NT, bool PERM>
__device__ __forceinline__ void stage128_tf32(uint32_t* S, const float* __restrict__ g,
                                              int gstride, int nrows) {
#pragma unroll
    for (int i = 0; i < 4096 / NT; i++) {
        int idx = threadIdx.x + i * NT;
        int r = idx >> 5, k4 = idx & 31;
        int rl = PERM ? permL(r) : r;
        float4 v = make_float4(0.f, 0.f, 0.f, 0.f);
        if (rl < nrows) v = *(const float4*)(g + (size_t)rl * gstride + k4 * 4);
        uint4 w;
        w.x = cvt_tf32(v.x); w.y = cvt_tf32(v.y);
        w.z = cvt_tf32(v.z); w.w = cvt_tf32(v.w);
        *(uint4*)(S + r * LDT + k4 * 4) = w;
    }
}

// ---------------- setup kernels ----------------------------------------------
__global__ void k_zero() {
    int i = blockIdx.x * blockDim.x + threadIdx.x;
    ((float4*)g_mnode)[i] = make_float4(0.f, 0.f, 0.f, 0.f);
}
__global__ void k_zero_hist() {
    int i = blockIdx.x * blockDim.x + threadIdx.x;
    if (i < NN) g_histD[i] = 0;
    else if (i < 2 * NN) g_histS[i - NN] = 0;
}
__global__ void k_hist(const int* __restrict__ dst, const int* __restrict__ src) {
    int e = blockIdx.x * 256 + threadIdx.x;
    atomicAdd(&g_histD[dst[e]], 1);
    atomicAdd(&g_histS[src[e]], 1);
}
__global__ void k_scan1024(const int* __restrict__ hist, int* __restrict__ start,
                           int* __restrict__ work) {
    __shared__ int part[1024];
    int tid = threadIdx.x;
    int base = tid * 40;
    int s = 0;
    for (int i = 0; i < 40; i++) {
        int b = base + i;
        if (b < NN) s += hist[b];
    }
    part[tid] = s;
    __syncthreads();
    for (int off = 1; off < 1024; off <<= 1) {
        int t = (tid >= off) ? part[tid - off] : 0;
        __syncthreads();
        part[tid] += t;
        __syncthreads();
    }
    int run = part[tid] - s;  // exclusive prefix
    for (int i = 0; i < 40; i++) {
        int b = base + i;
        if (b < NN) {
            start[b] = run;
            work[b] = run;
            run += hist[b];
        }
    }
    if (tid == 1023) start[NN] = part[1023];
}
__global__ void k_scatter(const int* __restrict__ dst, const int* __restrict__ src) {
    int e = blockIdx.x * 256 + threadIdx.x;
    int d = dst[e], s = src[e];
    int pd = atomicAdd(&g_workD[d], 1);
    g_permD[pd] = e;
    g_sdstD[pd] = d;
    g_ssrcD[pd] = s;
    int ps = atomicAdd(&g_workS[s], 1);
    g_permS[ps] = e;
}

// ---------------- node GEMM (256 thr, warps 4x2, 128x128 tile) ---------------
__device__ __forceinline__ void mma_core_256(const uint32_t* __restrict__ As,
                                             const uint32_t* __restrict__ Bs, int lane,
                                             int wm, int wn, float acc[2][8][4]) {
    int g = lane >> 2, tt = lane & 3;
    const uint32_t* ab = As + (wm * 32 + g) * LDT + tt;
    const uint32_t* bb = Bs + (wn * 64 + g) * LDT + tt;
#pragma unroll
    for (int ks = 0; ks < 16; ks++) {
        int k0 = ks * 8;
        uint32_t b[8][2];
#pragma unroll
        for (int nt = 0; nt < 8; nt++) {
            b[nt][0] = bb[nt * 8 * LDT + k0];
            b[nt][1] = bb[nt * 8 * LDT + k0 + 4];
        }
#pragma unroll
        for (int mt = 0; mt < 2; mt++) {
            uint32_t a0 = ab[(mt * 16 + 0) * LDT + k0];
            uint32_t a1 = ab[(mt * 16 + 8) * LDT + k0];
            uint32_t a2 = ab[(mt * 16 + 0) * LDT + k0 + 4];
            uint32_t a3 = ab[(mt * 16 + 8) * LDT + k0 + 4];
#pragma unroll
            for (int nt = 0; nt < 8; nt++) mma8(acc[mt][nt], a0, a1, a2, a3, b[nt][0], b[nt][1]);
        }
    }
}

__global__ void __launch_bounds__(256, 1) k_xab_mma(const float* __restrict__ x,
                                                    const float* __restrict__ W1) {
    extern __shared__ uint32_t sm[];
    uint32_t* Bs = sm;
    uint32_t* As = sm + TW;
    int lane = threadIdx.x & 31, wid = threadIdx.x >> 5;
    int wm = wid & 3, wn = wid >> 2;
    int half = blockIdx.y;
    int m0 = blockIdx.x * 128;
    int nrows = NN - m0 < 128 ? NN - m0 : 128;

    stage128_tf32<256, true>(Bs, W1 + half * 128, 384, 128);
    stage128_tf32<256, false>(As, x + (size_t)m0 * 128, 128, nrows);
    __syncthreads();

    float acc[2][8][4] = {};
    mma_core_256(As, Bs, lane, wm, wn, acc);

    int g = lane >> 2, tt = lane & 3;
#pragma unroll
    for (int mt = 0; mt < 2; mt++)
#pragma unroll
        for (int i = 0; i < 2; i++) {
            int r = m0 + wm * 32 + mt * 16 + g + i * 8;
            if (r < NN) {
                float* op = g_xab + (size_t)r * 256 + half * 128;
#pragma unroll
                for (int nt = 0; nt < 8; nt++) {
                    int col = permL(wn * 64 + nt * 8 + tt * 2);
                    *(float2*)(op + col) =
                        make_float2(acc[mt][nt][2 * i], acc[mt][nt][2 * i + 1]);
                }
            }
        }
}

__global__ void __launch_bounds__(256, 1) k_p_mma(const float* __restrict__ W2) {
    extern __shared__ uint32_t sm[];
    uint32_t* Bs = sm;
    uint32_t* As = sm + TW;
    int lane = threadIdx.x & 31, wid = threadIdx.x >> 5;
    int wm = wid & 3, wn = wid >> 2;
    int m0 = blockIdx.x * 128;
    int nrows = NN - m0 < 128 ? NN - m0 : 128;

    stage128_tf32<256, false>(Bs, W2, 128, 128);
    stage128_tf32<256, false>(As, g_mnode + (size_t)m0 * 128, 128, nrows);
    __syncthreads();

    float acc[2][8][4] = {};
    mma_core_256(As, Bs, lane, wm, wn, acc);

    int g = lane >> 2, tt = lane & 3;
#pragma unroll
    for (int mt = 0; mt < 2; mt++)
#pragma unroll
        for (int i = 0; i < 2; i++) {
            int r = m0 + wm * 32 + mt * 16 + g + i * 8;
            if (r < NN) {
                float* op = g_p + (size_t)r * 128 + wn * 64 + tt * 2;
#pragma unroll
                for (int nt = 0; nt < 8; nt++)
                    *(float2*)(op + nt * 8) =
                        make_float2(acc[mt][nt][2 * i], acc[mt][nt][2 * i + 1]);
            }
        }
}

// ---------------- edge kernel: sorted edges, run-shared epilogue -------------
// Row slot r holds sorted edge index j(r) = (r>>5)*32 + 4*(r&7) + ((r>>3)&3),
// so each thread's 4 fragment rows are 4 CONSECUTIVE sorted edges.
__global__ void __launch_bounds__(512, 1) k_edge(const float* __restrict__ h,
                                                 const float* __restrict__ W1) {
    extern __shared__ uint32_t sm[];
    uint32_t* Bs = sm;
    uint32_t* A[2] = {sm + TW, sm + 2 * TW};
    int* idxb[2] = {(int*)(sm + 3 * TW), (int*)(sm + 3 * TW) + 256};
    uint32_t sb = smem_u32(sm);
    const uint32_t A_OFF[2] = {sb + TW * 4, sb + 2 * TW * 4};
    const uint32_t IDX_OFF[2] = {sb + 3 * TW * 4, sb + 3 * TW * 4 + 1024};

    int tid = threadIdx.x, lane = tid & 31, wid = tid >> 5;
    int wm = wid & 3, wn = wid >> 2;
    int g = lane >> 2, tt = lane & 3;

    stage128_tf32<512, true>(Bs, W1 + 256, 384, 128);  // C block, rows permuted

    const int G = gridDim.x;
    const int T = (5000 - blockIdx.x + G - 1) / G;

    // staging thread map: row r = tid>>2; quad member q = tid&3 covers 128B
    int srow = tid >> 2, sq = tid & 3;
    int sj = ((srow >> 5) << 5) + ((srow & 7) << 2) + ((srow >> 3) & 3);

    // prologue: tile 0 -> buf 0
    {
        int e0 = blockIdx.x * 128;
        int edge = g_permD[e0 + sj];
        const float* hp = h + (size_t)edge * 128 + sq * 32;
        uint32_t sd = A_OFF[0] + (uint32_t)(srow * LDT) * 4 + sq * 128;
#pragma unroll
        for (int i = 0; i < 8; i++) cpa16(sd + i * 16, hp + i * 4);
        if (tid < 32) cpa16(IDX_OFF[0] + tid * 16, g_sdstD + e0 + tid * 4);
        else if (tid < 64) cpa16(IDX_OFF[0] + 512 + (tid - 32) * 16, g_ssrcD + e0 + (tid - 32) * 4);
        cpa_commit();
    }

    for (int t = 0; t < T; t++) {
        int cur = t & 1;
        if (t + 1 < T) {
            int e0 = (blockIdx.x + (size_t)(t + 1) * G) * 128;
            int edge = g_permD[e0 + sj];
            const float* hp = h + (size_t)edge * 128 + sq * 32;
            uint32_t sd = A_OFF[1 - cur] + (uint32_t)(srow * LDT) * 4 + sq * 128;
#pragma unroll
            for (int i = 0; i < 8; i++) cpa16(sd + i * 16, hp + i * 4);
            if (tid < 32) cpa16(IDX_OFF[1 - cur] + tid * 16, g_sdstD + e0 + tid * 4);
            else if (tid < 64)
                cpa16(IDX_OFF[1 - cur] + 512 + (tid - 32) * 16, g_ssrcD + e0 + (tid - 32) * 4);
            cpa_commit();
            asm volatile("cp.async.wait_group 1;" ::: "memory");
        } else {
            asm volatile("cp.async.wait_group 0;" ::: "memory");
        }
        __syncthreads();

        // mma with rna rounding applied to A fragments at load
        float acc[2][4][4] = {};
        {
            const uint32_t* ab = A[cur] + (wm * 32 + g) * LDT + tt;
            const uint32_t* bb = Bs + (wn * 32 + g) * LDT + tt;
#pragma unroll
            for (int ks = 0; ks < 16; ks++) {
                int k0 = ks * 8;
                uint32_t b[4][2];
#pragma unroll
                for (int nt = 0; nt < 4; nt++) {
                    b[nt][0] = bb[nt * 8 * LDT + k0];
                    b[nt][1] = bb[nt * 8 * LDT + k0 + 4];
                }
#pragma unroll
                for (int mt = 0; mt < 2; mt++) {
                    uint32_t a0 = cvt_tf32(__uint_as_float(ab[(mt * 16 + 0) * LDT + k0]));
                    uint32_t a1 = cvt_tf32(__uint_as_float(ab[(mt * 16 + 8) * LDT + k0]));
                    uint32_t a2 = cvt_tf32(__uint_as_float(ab[(mt * 16 + 0) * LDT + k0 + 4]));
                    uint32_t a3 = cvt_tf32(__uint_as_float(ab[(mt * 16 + 8) * LDT + k0 + 4]));
#pragma unroll
                    for (int nt = 0; nt < 4; nt++)
                        mma8(acc[mt][nt], a0, a1, a2, a3, b[nt][0], b[nt][1]);
                }
            }
        }

        // thread's 4 consecutive sorted edges: jb .. jb+3
        int jb = wm * 32 + 4 * g;
        int4 dd = *(const int4*)(idxb[cur] + jb);
        int4 ss = *(const int4*)(idxb[cur] + 128 + jb);
        __syncthreads();  // all warps done reading A[cur]/idx[cur]

        // epilogue: register segment-accumulation, red once per distinct dst
        int col0 = wn * 32 + tt * 4;
        int de[4] = {dd.x, dd.y, dd.z, dd.w};
        int se[4] = {ss.x, ss.y, ss.z, ss.w};
        int curd = de[0];
        const float* xaB = g_xab + (size_t)curd * 256 + col0;
        float4 A0 = *(const float4*)xaB;
        float4 A1 = *(const float4*)(xaB + 16);
        float4 ac0 = make_float4(0.f, 0.f, 0.f, 0.f);
        float4 ac1 = make_float4(0.f, 0.f, 0.f, 0.f);
#pragma unroll
        for (int c = 0; c < 4; c++) {
            int d = de[c];
            if (d != curd) {
                float* mp = g_mnode + (size_t)curd * 128 + col0;
                redv4(mp, ac0);
                redv4(mp + 16, ac1);
                curd = d;
                const float* xn = g_xab + (size_t)d * 256 + col0;
                A0 = *(const float4*)xn;
                A1 = *(const float4*)(xn + 16);
                ac0 = make_float4(0.f, 0.f, 0.f, 0.f);
                ac1 = make_float4(0.f, 0.f, 0.f, 0.f);
            }
            const float* xbB = g_xab + (size_t)se[c] * 256 + 128 + col0;
            float4 B0 = *(const float4*)xbB;
            float4 B1 = *(const float4*)(xbB + 16);
            int mt = c >> 1, i2 = (c & 1) * 2;
            ac0.x += fmaxf(acc[mt][0][i2] + A0.x + B0.x, 0.f);
            ac0.y += fmaxf(acc[mt][0][i2 + 1] + A0.y + B0.y, 0.f);
            ac0.z += fmaxf(acc[mt][1][i2] + A0.z + B0.z, 0.f);
            ac0.w += fmaxf(acc[mt][1][i2 + 1] + A0.w + B0.w, 0.f);
            ac1.x += fmaxf(acc[mt][2][i2] + A1.x + B1.x, 0.f);
            ac1.y += fmaxf(acc[mt][2][i2 + 1] + A1.y + B1.y, 0.f);
            ac1.z += fmaxf(acc[mt][3][i2] + A1.z + B1.z, 0.f);
            ac1.w += fmaxf(acc[mt][3][i2 + 1] + A1.w + B1.w, 0.f);
        }
        float* mp = g_mnode + (size_t)curd * 128 + col0;
        redv4(mp, ac0);
        redv4(mp + 16, ac1);
    }
}

// ---------------- LN: warp per node over src-CSR ------------------------------
__global__ void __launch_bounds__(256) k_ln_node(const float* __restrict__ snorm,
                                                 const float* __restrict__ gamma,
                                                 const float* __restrict__ beta,
                                                 float* __restrict__ out) {
    int wid = threadIdx.x >> 5, lane = threadIdx.x & 31;
    int v = blockIdx.x * 8 + wid;
    int beg = g_startS[v], end = g_startS[v + 1];
    if (beg == end) return;

    float4 pv = ((const float4*)(g_p + (size_t)v * 128))[lane];
    float sum = pv.x + pv.y + pv.z + pv.w;
    float ssq = pv.x * pv.x + pv.y * pv.y + pv.z * pv.z + pv.w * pv.w;
#pragma unroll
    for (int o = 16; o > 0; o >>= 1) {
        sum += __shfl_xor_sync(0xffffffffu, sum, o);
        ssq += __shfl_xor_sync(0xffffffffu, ssq, o);
    }
    float mu = sum * 0.0078125f;
    float var = ssq * 0.0078125f - mu * mu;
    float4 gg = ((const float4*)gamma)[lane];
    float4 bb = ((const float4*)beta)[lane];
    float4 pm = make_float4(pv.x - mu, pv.y - mu, pv.z - mu, pv.w - mu);

    for (int q = beg; q < end; q++) {
        int e = g_permS[q];
        float s = snorm[e];
        float ts = s * rsqrtf(var * s * s + 1e-5f);
        float4 o4;
        o4.x = fmaxf(pm.x * ts * gg.x + bb.x, 0.f);
        o4.y = fmaxf(pm.y * ts * gg.y + bb.y, 0.f);
        o4.z = fmaxf(pm.z * ts * gg.z + bb.z, 0.f);
        o4.w = fmaxf(pm.w * ts * gg.w + bb.w, 0.f);
        ((float4*)(out + (size_t)e * 128))[lane] = o4;
    }
}

// ---------------------------------------------------------------------------
extern "C" void kernel_launch(void* const* d_in, const int* in_sizes, int n_in,
                              void* d_out, int out_size) {
    const float* x = (const float*)d_in[0];
    const float* h = (const float*)d_in[1];
    const float* snorm_n = (const float*)d_in[2];
    const float* W1 = (const float*)d_in[4];
    const float* W2 = (const float*)d_in[5];
    const float* gamma = (const float*)d_in[6];
    const float* beta = (const float*)d_in[7];
    const int* src = (const int*)d_in[8];
    const int* dst = (const int*)d_in[9];
    float* out = (float*)d_out;

    cudaFuncSetAttribute(k_xab_mma, cudaFuncAttributeMaxDynamicSharedMemorySize, XAB_SMEM);
    cudaFuncSetAttribute(k_p_mma, cudaFuncAttributeMaxDynamicSharedMemorySize, XAB_SMEM);
    cudaFuncSetAttribute(k_edge, cudaFuncAttributeMaxDynamicSharedMemorySize, EDGE_SMEM);

    int* pD;
    int* pS;
    cudaGetSymbolAddress((void**)&pD, g_histD);
    cudaGetSymbolAddress((void**)&pS, g_histS);
    int* wD;
    int* wS;
    cudaGetSymbolAddress((void**)&wD, g_workD);
    cudaGetSymbolAddress((void**)&wS, g_workS);
    int* sD;
    int* sS;
    cudaGetSymbolAddress((void**)&sD, g_startD);
    cudaGetSymbolAddress((void**)&sS, g_startS);

    k_zero<<<5000, 256>>>();
    k_zero_hist<<<79, 1024>>>();
    k_hist<<<2500, 256>>>(dst, src);
    k_scan1024<<<1, 1024>>>(pD, sD, wD);
    k_scan1024<<<1, 1024>>>(pS, sS, wS);
    k_scatter<<<2500, 256>>>(dst, src);
    k_xab_mma<<<dim3(313, 2), 256, XAB_SMEM>>>(x, W1);
    k_edge<<<148, 512, EDGE_SMEM>>>(h, W1);
    k_p_mma<<<313, 256, XAB_SMEM>>>(W2);
    k_ln_node<<<5000, 256>>>(snorm_n, gamma, beta, out);
}

// round 7
// speedup vs baseline: 1.2353x; 1.2353x over previous
#include <cuda_runtime.h>
#include <cstdint>

// ---------------------------------------------------------------------------
// D_MPNNLayer on GB300 (sm_103a via compute_103 -> mma.sync tf32)
// Dst-sorted edges (register segment accumulation) + src-CSR LayerNorm.
// Fast multi-CTA scan preprocessing (round 6's single-CTA scan was 2x60us).
// ---------------------------------------------------------------------------

constexpr int NN = 40000;
constexpr int NE = 640000;

constexpr int LDT = 132;
constexpr int TW = 128 * LDT;
constexpr int EDGE_SMEM = (3 * TW) * 4 + 2048;
constexpr int XAB_SMEM = (2 * TW) * 4;

__device__ float g_xab[(size_t)NN * 256];
__device__ float g_mnode[(size_t)NN * 128];
__device__ float g_p[(size_t)NN * 128];

__device__ int g_histD[NN], g_histS[NN];
__device__ int g_workD[NN], g_workS[NN];
__device__ int g_startD[NN + 8], g_startS[NN + 8];
__device__ int g_bsum[80];
__device__ int g_permD[NE], g_permS[NE];
__device__ int g_sdstD[NE], g_ssrcD[NE];

__device__ __host__ __forceinline__ int permL(int r) {
    return (r & 0x61) | ((r >> 2) & 0x02) | ((r & 0x06) << 1) | (r & 0x10);
}

// ---------------- helpers ----------------------------------------------------
__device__ __forceinline__ uint32_t smem_u32(const void* p) {
    uint32_t a;
    asm("{ .reg .u64 t; cvta.to.shared.u64 t, %1; cvt.u32.u64 %0, t; }" : "=r"(a) : "l"(p));
    return a;
}
__device__ __forceinline__ uint32_t cvt_tf32(float f) {
    uint32_t r;
    asm("cvt.rna.tf32.f32 %0, %1;" : "=r"(r) : "f"(f));
    return r;
}
__device__ __forceinline__ void cpa16(uint32_t s, const void* g) {
    asm volatile("cp.async.cg.shared.global [%0], [%1], 16;" ::"r"(s), "l"(g));
}
__device__ __forceinline__ void cpa_commit() {
    asm volatile("cp.async.commit_group;" ::: "memory");
}
__device__ __forceinline__ void mma8(float acc[4], uint32_t a0, uint32_t a1, uint32_t a2,
                                     uint32_t a3, uint32_t b0, uint32_t b1) {
    asm("mma.sync.aligned.m16n8k8.row.col.f32.tf32.tf32.f32 "
        "{%0,%1,%2,%3}, {%4,%5,%6,%7}, {%8,%9}, {%0,%1,%2,%3};"
        : "+f"(acc[0]), "+f"(acc[1]), "+f"(acc[2]), "+f"(acc[3])
        : "r"(a0), "r"(a1), "r"(a2), "r"(a3), "r"(b0), "r"(b1));
}
__device__ __forceinline__ void redv4(float* p, float4 v) {
    asm volatile("red.global.add.v4.f32 [%0], {%1,%2,%3,%4};" ::"l"(p), "f"(v.x), "f"(v.y),
                 "f"(v.z), "f"(v.w)
                 : "memory");
}

template <int NT, bool PERM>
__device__ __forceinline__ void stage128_tf32(uint32_t* S, const float* __restrict__ g,
                                              int gstride, int nrows) {
#pragma unroll
    for (int i = 0; i < 4096 / NT; i++) {
        int idx = threadIdx.x + i * NT;
        int r = idx >> 5, k4 = idx & 31;
        int rl = PERM ? permL(r) : r;
        float4 v = make_float4(0.f, 0.f, 0.f, 0.f);
        if (rl < nrows) v = *(const float4*)(g + (size_t)rl * gstride + k4 * 4);
        uint4 w;
        w.x = cvt_tf32(v.x); w.y = cvt_tf32(v.y);
        w.z = cvt_tf32(v.z); w.w = cvt_tf32(v.w);
        *(uint4*)(S + r * LDT + k4 * 4) = w;
    }
}

// ---------------- preprocessing -----------------------------------------------
__global__ void k_hist(const int* __restrict__ dst, const int* __restrict__ src) {
    int e = blockIdx.x * 256 + threadIdx.x;
    atomicAdd(&g_histD[dst[e]], 1);
    atomicAdd(&g_histS[src[e]], 1);
}

// Phase A: CTA-local exclusive scan of 1000 nodes; block total -> g_bsum
__global__ void __launch_bounds__(1024) k_scan_local() {
    __shared__ int sc[1024];
    int gy = blockIdx.y, bx = blockIdx.x, tid = threadIdx.x;
    int base = bx * 1000;
    const int* hist = gy ? g_histS : g_histD;
    int* start = gy ? g_startS : g_startD;
    int v = (tid < 1000) ? hist[base + tid] : 0;
    sc[tid] = v;
    __syncthreads();
#pragma unroll
    for (int off = 1; off < 1024; off <<= 1) {
        int t = (tid >= off) ? sc[tid - off] : 0;
        __syncthreads();
        sc[tid] += t;
        __syncthreads();
    }
    if (tid < 1000) start[base + tid] = sc[tid] - v;  // local exclusive
    if (tid == 1023) g_bsum[gy * 40 + bx] = sc[1023];
}

// Phase B: scan the 2x40 block sums (independent halves)
__global__ void __launch_bounds__(128) k_scan_bsum() {
    __shared__ int sc[128];
    int tid = threadIdx.x;
    int half = tid >> 6, loc = tid & 63;
    int v = (loc < 40) ? g_bsum[half * 40 + loc] : 0;
    sc[tid] = v;
    __syncthreads();
#pragma unroll
    for (int off = 1; off < 64; off <<= 1) {
        int t = (loc >= off) ? sc[tid - off] : 0;
        __syncthreads();
        sc[tid] += t;
        __syncthreads();
    }
    if (loc < 40) g_bsum[half * 40 + loc] = sc[tid] - v;  // exclusive
    if (loc == 63) {
        if (half == 0) g_startD[NN] = sc[tid];
        else g_startS[NN] = sc[tid];
    }
}

// Phase C: add block offset; init work
__global__ void __launch_bounds__(1024) k_scan_add() {
    int gy = blockIdx.y, bx = blockIdx.x, tid = threadIdx.x;
    if (tid >= 1000) return;
    int base = bx * 1000;
    int* start = gy ? g_startS : g_startD;
    int* work = gy ? g_workS : g_workD;
    int v = start[base + tid] + g_bsum[gy * 40 + bx];
    start[base + tid] = v;
    work[base + tid] = v;
}

__global__ void k_scatter(const int* __restrict__ dst, const int* __restrict__ src) {
    int e = blockIdx.x * 256 + threadIdx.x;
    int d = dst[e], s = src[e];
    int pd = atomicAdd(&g_workD[d], 1);
    g_permD[pd] = e;
    g_sdstD[pd] = d;
    g_ssrcD[pd] = s;
    int ps = atomicAdd(&g_workS[s], 1);
    g_permS[ps] = e;
}

// ---------------- node GEMMs ---------------------------------------------------
__device__ __forceinline__ void mma_core_256(const uint32_t* __restrict__ As,
                                             const uint32_t* __restrict__ Bs, int lane,
                                             int wm, int wn, float acc[2][8][4]) {
    int g = lane >> 2, tt = lane & 3;
    const uint32_t* ab = As + (wm * 32 + g) * LDT + tt;
    const uint32_t* bb = Bs + (wn * 64 + g) * LDT + tt;
#pragma unroll
    for (int ks = 0; ks < 16; ks++) {
        int k0 = ks * 8;
        uint32_t b[8][2];
#pragma unroll
        for (int nt = 0; nt < 8; nt++) {
            b[nt][0] = bb[nt * 8 * LDT + k0];
            b[nt][1] = bb[nt * 8 * LDT + k0 + 4];
        }
#pragma unroll
        for (int mt = 0; mt < 2; mt++) {
            uint32_t a0 = ab[(mt * 16 + 0) * LDT + k0];
            uint32_t a1 = ab[(mt * 16 + 8) * LDT + k0];
            uint32_t a2 = ab[(mt * 16 + 0) * LDT + k0 + 4];
            uint32_t a3 = ab[(mt * 16 + 8) * LDT + k0 + 4];
#pragma unroll
            for (int nt = 0; nt < 8; nt++) mma8(acc[mt][nt], a0, a1, a2, a3, b[nt][0], b[nt][1]);
        }
    }
}

__global__ void __launch_bounds__(256, 1) k_xab_mma(const float* __restrict__ x,
                                                    const float* __restrict__ W1) {
    extern __shared__ uint32_t sm[];
    uint32_t* Bs = sm;
    uint32_t* As = sm + TW;
    int lane = threadIdx.x & 31, wid = threadIdx.x >> 5;
    int wm = wid & 3, wn = wid >> 2;
    int half = blockIdx.y;
    int m0 = blockIdx.x * 128;
    int nrows = NN - m0 < 128 ? NN - m0 : 128;

    stage128_tf32<256, true>(Bs, W1 + half * 128, 384, 128);
    stage128_tf32<256, false>(As, x + (size_t)m0 * 128, 128, nrows);
    __syncthreads();

    float acc[2][8][4] = {};
    mma_core_256(As, Bs, lane, wm, wn, acc);

    int g = lane >> 2, tt = lane & 3;
#pragma unroll
    for (int mt = 0; mt < 2; mt++)
#pragma unroll
        for (int i = 0; i < 2; i++) {
            int r = m0 + wm * 32 + mt * 16 + g + i * 8;
            if (r < NN) {
                float* op = g_xab + (size_t)r * 256 + half * 128;
#pragma unroll
                for (int nt = 0; nt < 8; nt++) {
                    int col = permL(wn * 64 + nt * 8 + tt * 2);
                    *(float2*)(op + col) =
                        make_float2(acc[mt][nt][2 * i], acc[mt][nt][2 * i + 1]);
                }
            }
        }
}

__global__ void __launch_bounds__(256, 1) k_p_mma(const float* __restrict__ W2) {
    extern __shared__ uint32_t sm[];
    uint32_t* Bs = sm;
    uint32_t* As = sm + TW;
    int lane = threadIdx.x & 31, wid = threadIdx.x >> 5;
    int wm = wid & 3, wn = wid >> 2;
    int m0 = blockIdx.x * 128;
    int nrows = NN - m0 < 128 ? NN - m0 : 128;

    stage128_tf32<256, false>(Bs, W2, 128, 128);
    stage128_tf32<256, false>(As, g_mnode + (size_t)m0 * 128, 128, nrows);
    __syncthreads();

    float acc[2][8][4] = {};
    mma_core_256(As, Bs, lane, wm, wn, acc);

    int g = lane >> 2, tt = lane & 3;
#pragma unroll
    for (int mt = 0; mt < 2; mt++)
#pragma unroll
        for (int i = 0; i < 2; i++) {
            int r = m0 + wm * 32 + mt * 16 + g + i * 8;
            if (r < NN) {
                float* op = g_p + (size_t)r * 128 + wn * 64 + tt * 2;
#pragma unroll
                for (int nt = 0; nt < 8; nt++)
                    *(float2*)(op + nt * 8) =
                        make_float2(acc[mt][nt][2 * i], acc[mt][nt][2 * i + 1]);
            }
        }
}

// ---------------- edge kernel: sorted edges, run-shared epilogue -------------
__global__ void __launch_bounds__(512, 1) k_edge(const float* __restrict__ h,
                                                 const float* __restrict__ W1) {
    extern __shared__ uint32_t sm[];
    uint32_t* Bs = sm;
    uint32_t* A[2] = {sm + TW, sm + 2 * TW};
    int* idxb[2] = {(int*)(sm + 3 * TW), (int*)(sm + 3 * TW) + 256};
    uint32_t sb = smem_u32(sm);
    const uint32_t A_OFF[2] = {sb + TW * 4, sb + 2 * TW * 4};
    const uint32_t IDX_OFF[2] = {sb + 3 * TW * 4, sb + 3 * TW * 4 + 1024};

    int tid = threadIdx.x, lane = tid & 31, wid = tid >> 5;
    int wm = wid & 3, wn = wid >> 2;
    int g = lane >> 2, tt = lane & 3;

    stage128_tf32<512, true>(Bs, W1 + 256, 384, 128);

    const int G = gridDim.x;
    const int T = (5000 - blockIdx.x + G - 1) / G;

    int srow = tid >> 2, sq = tid & 3;
    int sj = ((srow >> 5) << 5) + ((srow & 7) << 2) + ((srow >> 3) & 3);

    {
        int e0 = blockIdx.x * 128;
        int edge = g_permD[e0 + sj];
        const float* hp = h + (size_t)edge * 128 + sq * 32;
        uint32_t sd = A_OFF[0] + (uint32_t)(srow * LDT) * 4 + sq * 128;
#pragma unroll
        for (int i = 0; i < 8; i++) cpa16(sd + i * 16, hp + i * 4);
        if (tid < 32) cpa16(IDX_OFF[0] + tid * 16, g_sdstD + e0 + tid * 4);
        else if (tid < 64) cpa16(IDX_OFF[0] + 512 + (tid - 32) * 16, g_ssrcD + e0 + (tid - 32) * 4);
        cpa_commit();
    }

    for (int t = 0; t < T; t++) {
        int cur = t & 1;
        if (t + 1 < T) {
            int e0 = (blockIdx.x + (size_t)(t + 1) * G) * 128;
            int edge = g_permD[e0 + sj];
            const float* hp = h + (size_t)edge * 128 + sq * 32;
            uint32_t sd = A_OFF[1 - cur] + (uint32_t)(srow * LDT) * 4 + sq * 128;
#pragma unroll
            for (int i = 0; i < 8; i++) cpa16(sd + i * 16, hp + i * 4);
            if (tid < 32) cpa16(IDX_OFF[1 - cur] + tid * 16, g_sdstD + e0 + tid * 4);
            else if (tid < 64)
                cpa16(IDX_OFF[1 - cur] + 512 + (tid - 32) * 16, g_ssrcD + e0 + (tid - 32) * 4);
            cpa_commit();
            asm volatile("cp.async.wait_group 1;" ::: "memory");
        } else {
            asm volatile("cp.async.wait_group 0;" ::: "memory");
        }
        __syncthreads();

        float acc[2][4][4] = {};
        {
            const uint32_t* ab = A[cur] + (wm * 32 + g) * LDT + tt;
            const uint32_t* bb = Bs + (wn * 32 + g) * LDT + tt;
#pragma unroll
            for (int ks = 0; ks < 16; ks++) {
                int k0 = ks * 8;
                uint32_t b[4][2];
#pragma unroll
                for (int nt = 0; nt < 4; nt++) {
                    b[nt][0] = bb[nt * 8 * LDT + k0];
                    b[nt][1] = bb[nt * 8 * LDT + k0 + 4];
                }
#pragma unroll
                for (int mt = 0; mt < 2; mt++) {
                    uint32_t a0 = cvt_tf32(__uint_as_float(ab[(mt * 16 + 0) * LDT + k0]));
                    uint32_t a1 = cvt_tf32(__uint_as_float(ab[(mt * 16 + 8) * LDT + k0]));
                    uint32_t a2 = cvt_tf32(__uint_as_float(ab[(mt * 16 + 0) * LDT + k0 + 4]));
                    uint32_t a3 = cvt_tf32(__uint_as_float(ab[(mt * 16 + 8) * LDT + k0 + 4]));
#pragma unroll
                    for (int nt = 0; nt < 4; nt++)
                        mma8(acc[mt][nt], a0, a1, a2, a3, b[nt][0], b[nt][1]);
                }
            }
        }

        int jb = wm * 32 + 4 * g;
        int4 dd = *(const int4*)(idxb[cur] + jb);
        int4 ss = *(const int4*)(idxb[cur] + 128 + jb);
        __syncthreads();

        int col0 = wn * 32 + tt * 4;
        int de[4] = {dd.x, dd.y, dd.z, dd.w};
        int se[4] = {ss.x, ss.y, ss.z, ss.w};
        int curd = de[0];
        const float* xaB = g_xab + (size_t)curd * 256 + col0;
        float4 A0 = *(const float4*)xaB;
        float4 A1 = *(const float4*)(xaB + 16);
        float4 ac0 = make_float4(0.f, 0.f, 0.f, 0.f);
        float4 ac1 = make_float4(0.f, 0.f, 0.f, 0.f);
#pragma unroll
        for (int c = 0; c < 4; c++) {
            int d = de[c];
            if (d != curd) {
                float* mp = g_mnode + (size_t)curd * 128 + col0;
                redv4(mp, ac0);
                redv4(mp + 16, ac1);
                curd = d;
                const float* xn = g_xab + (size_t)d * 256 + col0;
                A0 = *(const float4*)xn;
                A1 = *(const float4*)(xn + 16);
                ac0 = make_float4(0.f, 0.f, 0.f, 0.f);
                ac1 = make_float4(0.f, 0.f, 0.f, 0.f);
            }
            const float* xbB = g_xab + (size_t)se[c] * 256 + 128 + col0;
            float4 B0 = *(const float4*)xbB;
            float4 B1 = *(const float4*)(xbB + 16);
            int mt = c >> 1, i2 = (c & 1) * 2;
            ac0.x += fmaxf(acc[mt][0][i2] + A0.x + B0.x, 0.f);
            ac0.y += fmaxf(acc[mt][0][i2 + 1] + A0.y + B0.y, 0.f);
            ac0.z += fmaxf(acc[mt][1][i2] + A0.z + B0.z, 0.f);
            ac0.w += fmaxf(acc[mt][1][i2 + 1] + A0.w + B0.w, 0.f);
            ac1.x += fmaxf(acc[mt][2][i2] + A1.x + B1.x, 0.f);
            ac1.y += fmaxf(acc[mt][2][i2 + 1] + A1.y + B1.y, 0.f);
            ac1.z += fmaxf(acc[mt][3][i2] + A1.z + B1.z, 0.f);
            ac1.w += fmaxf(acc[mt][3][i2 + 1] + A1.w + B1.w, 0.f);
        }
        float* mp = g_mnode + (size_t)curd * 128 + col0;
        redv4(mp, ac0);
        redv4(mp + 16, ac1);
    }
}

// ---------------- LN: warp per node over src-CSR ------------------------------
__global__ void __launch_bounds__(256) k_ln_node(const float* __restrict__ snorm,
                                                 const float* __restrict__ gamma,
                                                 const float* __restrict__ beta,
                                                 float* __restrict__ out) {
    int wid = threadIdx.x >> 5, lane = threadIdx.x & 31;
    int v = blockIdx.x * 8 + wid;
    int beg = g_startS[v], end = g_startS[v + 1];
    if (beg == end) return;

    float4 pv = ((const float4*)(g_p + (size_t)v * 128))[lane];
    float sum = pv.x + pv.y + pv.z + pv.w;
    float ssq = pv.x * pv.x + pv.y * pv.y + pv.z * pv.z + pv.w * pv.w;
#pragma unroll
    for (int o = 16; o > 0; o >>= 1) {
        sum += __shfl_xor_sync(0xffffffffu, sum, o);
        ssq += __shfl_xor_sync(0xffffffffu, ssq, o);
    }
    float mu = sum * 0.0078125f;
    float var = ssq * 0.0078125f - mu * mu;
    float4 gg = ((const float4*)gamma)[lane];
    float4 bb = ((const float4*)beta)[lane];
    float4 pm = make_float4(pv.x - mu, pv.y - mu, pv.z - mu, pv.w - mu);

    for (int q = beg; q < end; q++) {
        int e = g_permS[q];
        float s = snorm[e];
        float ts = s * rsqrtf(var * s * s + 1e-5f);
        float4 o4;
        o4.x = fmaxf(pm.x * ts * gg.x + bb.x, 0.f);
        o4.y = fmaxf(pm.y * ts * gg.y + bb.y, 0.f);
        o4.z = fmaxf(pm.z * ts * gg.z + bb.z, 0.f);
        o4.w = fmaxf(pm.w * ts * gg.w + bb.w, 0.f);
        ((float4*)(out + (size_t)e * 128))[lane] = o4;
    }
}

// ---------------------------------------------------------------------------
extern "C" void kernel_launch(void* const* d_in, const int* in_sizes, int n_in,
                              void* d_out, int out_size) {
    const float* x = (const float*)d_in[0];
    const float* h = (const float*)d_in[1];
    const float* snorm_n = (const float*)d_in[2];
    const float* W1 = (const float*)d_in[4];
    const float* W2 = (const float*)d_in[5];
    const float* gamma = (const float*)d_in[6];
    const float* beta = (const float*)d_in[7];
    const int* src = (const int*)d_in[8];
    const int* dst = (const int*)d_in[9];
    float* out = (float*)d_out;

    cudaFuncSetAttribute(k_xab_mma, cudaFuncAttributeMaxDynamicSharedMemorySize, XAB_SMEM);
    cudaFuncSetAttribute(k_p_mma, cudaFuncAttributeMaxDynamicSharedMemorySize, XAB_SMEM);
    cudaFuncSetAttribute(k_edge, cudaFuncAttributeMaxDynamicSharedMemorySize, EDGE_SMEM);

    void* mnode;
    void* histD;
    void* histS;
    cudaGetSymbolAddress(&mnode, g_mnode);
    cudaGetSymbolAddress(&histD, g_histD);
    cudaGetSymbolAddress(&histS, g_histS);

    cudaMemsetAsync(mnode, 0, (size_t)NN * 128 * 4);
    cudaMemsetAsync(histD, 0, NN * 4);
    cudaMemsetAsync(histS, 0, NN * 4);
    k_hist<<<2500, 256>>>(dst, src);
    k_scan_local<<<dim3(40, 2), 1024>>>();
    k_scan_bsum<<<1, 128>>>();
    k_scan_add<<<dim3(40, 2), 1024>>>();
    k_scatter<<<2500, 256>>>(dst, src);
    k_xab_mma<<<dim3(313, 2), 256, XAB_SMEM>>>(x, W1);
    k_edge<<<148, 512, EDGE_SMEM>>>(h, W1);
    k_p_mma<<<313, 256, XAB_SMEM>>>(W2);
    k_ln_node<<<5000, 256>>>(snorm_n, gamma, beta, out);
}

// round 8
// speedup vs baseline: 1.2951x; 1.0484x over previous
#include <cuda_runtime.h>
#include <cstdint>

// ---------------------------------------------------------------------------
// D_MPNNLayer on GB300 (sm_103a via compute_103 -> mma.sync)
// Edge GEMM in fp16 (m16n8k16, same 10-bit mantissa as tf32, half the ops).
// Dst-sorted edges (register segment accumulation) + src-CSR LayerNorm.
// ---------------------------------------------------------------------------

constexpr int NN = 40000;
constexpr int NE = 640000;

// tf32 node GEMMs
constexpr int LDT = 132;
constexpr int TW = 128 * LDT;
constexpr int XAB_SMEM = (2 * TW) * 4;

// fp16 edge GEMM: f16x2 words, row stride 68 words (272B, conflict-free frags)
constexpr int LDH = 68;
constexpr int THW = 128 * LDH;
constexpr int EDGE_SMEM = (3 * THW) * 4 + 2048;

__device__ float g_xab[(size_t)NN * 256];
__device__ float g_mnode[(size_t)NN * 128];
__device__ float g_p[(size_t)NN * 128];

__device__ int g_histD[NN], g_histS[NN];
__device__ int g_workD[NN], g_workS[NN];
__device__ int g_startD[NN + 8], g_startS[NN + 8];
__device__ int g_bsum[80];
__device__ int g_permD[NE], g_permS[NE];
__device__ int g_sdstD[NE], g_ssrcD[NE];

__device__ __host__ __forceinline__ int permL(int r) {
    return (r & 0x61) | ((r >> 2) & 0x02) | ((r & 0x06) << 1) | (r & 0x10);
}

// ---------------- helpers ----------------------------------------------------
__device__ __forceinline__ uint32_t cvt_tf32(float f) {
    uint32_t r;
    asm("cvt.rna.tf32.f32 %0, %1;" : "=r"(r) : "f"(f));
    return r;
}
__device__ __forceinline__ uint32_t pk_f16x2(float lo, float hi) {
    uint32_t r;
    asm("cvt.rn.f16x2.f32 %0, %1, %2;" : "=r"(r) : "f"(hi), "f"(lo));
    return r;
}
__device__ __forceinline__ void mma8(float acc[4], uint32_t a0, uint32_t a1, uint32_t a2,
                                     uint32_t a3, uint32_t b0, uint32_t b1) {
    asm("mma.sync.aligned.m16n8k8.row.col.f32.tf32.tf32.f32 "
        "{%0,%1,%2,%3}, {%4,%5,%6,%7}, {%8,%9}, {%0,%1,%2,%3};"
        : "+f"(acc[0]), "+f"(acc[1]), "+f"(acc[2]), "+f"(acc[3])
        : "r"(a0), "r"(a1), "r"(a2), "r"(a3), "r"(b0), "r"(b1));
}
__device__ __forceinline__ void mma16h(float acc[4], uint32_t a0, uint32_t a1, uint32_t a2,
                                       uint32_t a3, uint32_t b0, uint32_t b1) {
    asm("mma.sync.aligned.m16n8k16.row.col.f32.f16.f16.f32 "
        "{%0,%1,%2,%3}, {%4,%5,%6,%7}, {%8,%9}, {%0,%1,%2,%3};"
        : "+f"(acc[0]), "+f"(acc[1]), "+f"(acc[2]), "+f"(acc[3])
        : "r"(a0), "r"(a1), "r"(a2), "r"(a3), "r"(b0), "r"(b1));
}
__device__ __forceinline__ void redv4(float* p, float4 v) {
    asm volatile("red.global.add.v4.f32 [%0], {%1,%2,%3,%4};" ::"l"(p), "f"(v.x), "f"(v.y),
                 "f"(v.z), "f"(v.w)
                 : "memory");
}

template <int NT, bool PERM>
__device__ __forceinline__ void stage128_tf32(uint32_t* S, const float* __restrict__ g,
                                              int gstride, int nrows) {
#pragma unroll
    for (int i = 0; i < 4096 / NT; i++) {
        int idx = threadIdx.x + i * NT;
        int r = idx >> 5, k4 = idx & 31;
        int rl = PERM ? permL(r) : r;
        float4 v = make_float4(0.f, 0.f, 0.f, 0.f);
        if (rl < nrows) v = *(const float4*)(g + (size_t)rl * gstride + k4 * 4);
        uint4 w;
        w.x = cvt_tf32(v.x); w.y = cvt_tf32(v.y);
        w.z = cvt_tf32(v.z); w.w = cvt_tf32(v.w);
        *(uint4*)(S + r * LDT + k4 * 4) = w;
    }
}

// ---------------- preprocessing -----------------------------------------------
__global__ void k_hist(const int* __restrict__ dst, const int* __restrict__ src) {
    int e = blockIdx.x * 256 + threadIdx.x;
    atomicAdd(&g_histD[dst[e]], 1);
    atomicAdd(&g_histS[src[e]], 1);
}
__global__ void __launch_bounds__(1024) k_scan_local() {
    __shared__ int sc[1024];
    int gy = blockIdx.y, bx = blockIdx.x, tid = threadIdx.x;
    int base = bx * 1000;
    const int* hist = gy ? g_histS : g_histD;
    int* start = gy ? g_startS : g_startD;
    int v = (tid < 1000) ? hist[base + tid] : 0;
    sc[tid] = v;
    __syncthreads();
#pragma unroll
    for (int off = 1; off < 1024; off <<= 1) {
        int t = (tid >= off) ? sc[tid - off] : 0;
        __syncthreads();
        sc[tid] += t;
        __syncthreads();
    }
    if (tid < 1000) start[base + tid] = sc[tid] - v;
    if (tid == 1023) g_bsum[gy * 40 + bx] = sc[1023];
}
__global__ void __launch_bounds__(128) k_scan_bsum() {
    __shared__ int sc[128];
    int tid = threadIdx.x;
    int half = tid >> 6, loc = tid & 63;
    int v = (loc < 40) ? g_bsum[half * 40 + loc] : 0;
    sc[tid] = v;
    __syncthreads();
#pragma unroll
    for (int off = 1; off < 64; off <<= 1) {
        int t = (loc >= off) ? sc[tid - off] : 0;
        __syncthreads();
        sc[tid] += t;
        __syncthreads();
    }
    if (loc < 40) g_bsum[half * 40 + loc] = sc[tid] - v;
    if (loc == 63) {
        if (half == 0) g_startD[NN] = sc[tid];
        else g_startS[NN] = sc[tid];
    }
}
__global__ void __launch_bounds__(1024) k_scan_add() {
    int gy = blockIdx.y, bx = blockIdx.x, tid = threadIdx.x;
    if (tid >= 1000) return;
    int base = bx * 1000;
    int* start = gy ? g_startS : g_startD;
    int* work = gy ? g_workS : g_workD;
    int v = start[base + tid] + g_bsum[gy * 40 + bx];
    start[base + tid] = v;
    work[base + tid] = v;
}
__global__ void k_scatter(const int* __restrict__ dst, const int* __restrict__ src) {
    int e = blockIdx.x * 256 + threadIdx.x;
    int d = dst[e], s = src[e];
    int pd = atomicAdd(&g_workD[d], 1);
    g_permD[pd] = e;
    g_sdstD[pd] = d;
    g_ssrcD[pd] = s;
    int ps = atomicAdd(&g_workS[s], 1);
    g_permS[ps] = e;
}

// ---------------- node GEMMs (tf32, unchanged) --------------------------------
__device__ __forceinline__ void mma_core_256(const uint32_t* __restrict__ As,
                                             const uint32_t* __restrict__ Bs, int lane,
                                             int wm, int wn, float acc[2][8][4]) {
    int g = lane >> 2, tt = lane & 3;
    const uint32_t* ab = As + (wm * 32 + g) * LDT + tt;
    const uint32_t* bb = Bs + (wn * 64 + g) * LDT + tt;
#pragma unroll
    for (int ks = 0; ks < 16; ks++) {
        int k0 = ks * 8;
        uint32_t b[8][2];
#pragma unroll
        for (int nt = 0; nt < 8; nt++) {
            b[nt][0] = bb[nt * 8 * LDT + k0];
            b[nt][1] = bb[nt * 8 * LDT + k0 + 4];
        }
#pragma unroll
        for (int mt = 0; mt < 2; mt++) {
            uint32_t a0 = ab[(mt * 16 + 0) * LDT + k0];
            uint32_t a1 = ab[(mt * 16 + 8) * LDT + k0];
            uint32_t a2 = ab[(mt * 16 + 0) * LDT + k0 + 4];
            uint32_t a3 = ab[(mt * 16 + 8) * LDT + k0 + 4];
#pragma unroll
            for (int nt = 0; nt < 8; nt++) mma8(acc[mt][nt], a0, a1, a2, a3, b[nt][0], b[nt][1]);
        }
    }
}

__global__ void __launch_bounds__(256, 1) k_xab_mma(const float* __restrict__ x,
                                                    const float* __restrict__ W1) {
    extern __shared__ uint32_t sm[];
    uint32_t* Bs = sm;
    uint32_t* As = sm + TW;
    int lane = threadIdx.x & 31, wid = threadIdx.x >> 5;
    int wm = wid & 3, wn = wid >> 2;
    int half = blockIdx.y;
    int m0 = blockIdx.x * 128;
    int nrows = NN - m0 < 128 ? NN - m0 : 128;

    stage128_tf32<256, true>(Bs, W1 + half * 128, 384, 128);
    stage128_tf32<256, false>(As, x + (size_t)m0 * 128, 128, nrows);
    __syncthreads();

    float acc[2][8][4] = {};
    mma_core_256(As, Bs, lane, wm, wn, acc);

    int g = lane >> 2, tt = lane & 3;
#pragma unroll
    for (int mt = 0; mt < 2; mt++)
#pragma unroll
        for (int i = 0; i < 2; i++) {
            int r = m0 + wm * 32 + mt * 16 + g + i * 8;
            if (r < NN) {
                float* op = g_xab + (size_t)r * 256 + half * 128;
#pragma unroll
                for (int nt = 0; nt < 8; nt++) {
                    int col = permL(wn * 64 + nt * 8 + tt * 2);
                    *(float2*)(op + col) =
                        make_float2(acc[mt][nt][2 * i], acc[mt][nt][2 * i + 1]);
                }
            }
        }
}

__global__ void __launch_bounds__(256, 1) k_p_mma(const float* __restrict__ W2) {
    extern __shared__ uint32_t sm[];
    uint32_t* Bs = sm;
    uint32_t* As = sm + TW;
    int lane = threadIdx.x & 31, wid = threadIdx.x >> 5;
    int wm = wid & 3, wn = wid >> 2;
    int m0 = blockIdx.x * 128;
    int nrows = NN - m0 < 128 ? NN - m0 : 128;

    stage128_tf32<256, false>(Bs, W2, 128, 128);
    stage128_tf32<256, false>(As, g_mnode + (size_t)m0 * 128, 128, nrows);
    __syncthreads();

    float acc[2][8][4] = {};
    mma_core_256(As, Bs, lane, wm, wn, acc);

    int g = lane >> 2, tt = lane & 3;
#pragma unroll
    for (int mt = 0; mt < 2; mt++)
#pragma unroll
        for (int i = 0; i < 2; i++) {
            int r = m0 + wm * 32 + mt * 16 + g + i * 8;
            if (r < NN) {
                float* op = g_p + (size_t)r * 128 + wn * 64 + tt * 2;
#pragma unroll
                for (int nt = 0; nt < 8; nt++)
                    *(float2*)(op + nt * 8) =
                        make_float2(acc[mt][nt][2 * i], acc[mt][nt][2 * i + 1]);
            }
        }
}

// ---------------- edge kernel: fp16 mma, sorted edges, reg-prefetch staging ---
__global__ void __launch_bounds__(512, 1) k_edge(const float* __restrict__ h,
                                                 const float* __restrict__ W1) {
    extern __shared__ uint32_t sm[];
    uint32_t* Bs = sm;
    uint32_t* A[2] = {sm + THW, sm + 2 * THW};
    int* idxb[2] = {(int*)(sm + 3 * THW), (int*)(sm + 3 * THW) + 256};

    int tid = threadIdx.x, lane = tid & 31, wid = tid >> 5;
    int wm = wid & 3, wn = wid >> 2;
    int g = lane >> 2, tt = lane & 3;

    // staging map: row srow, column quarter sq (32 floats = 16 f16x2 words)
    int srow = tid >> 2, sq = tid & 3;
    int sj = ((srow & 7) << 2) + ((srow >> 3) & 3) + ((srow >> 5) << 5);

    // --- stage B = C block of W1 (rows permuted), fp16 ---
    {
        int rl = permL(srow);
        const float* wp = W1 + (size_t)rl * 384 + 256 + sq * 32;
        uint32_t w[16];
#pragma unroll
        for (int i = 0; i < 8; i++) {
            float4 v = *(const float4*)(wp + i * 4);
            w[2 * i] = pk_f16x2(v.x, v.y);
            w[2 * i + 1] = pk_f16x2(v.z, v.w);
        }
        uint4* dp = (uint4*)(Bs + srow * LDH + sq * 16);
#pragma unroll
        for (int j = 0; j < 4; j++) dp[j] = ((uint4*)w)[j];
    }

    const int G = gridDim.x;
    const int T = (5000 - blockIdx.x + G - 1) / G;

    // --- prologue: stage tile 0 synchronously ---
    {
        int e0 = blockIdx.x * 128;
        int edge = g_permD[e0 + sj];
        const float* hp = h + (size_t)edge * 128 + sq * 32;
        uint32_t w[16];
#pragma unroll
        for (int i = 0; i < 8; i++) {
            float4 v = *(const float4*)(hp + i * 4);
            w[2 * i] = pk_f16x2(v.x, v.y);
            w[2 * i + 1] = pk_f16x2(v.z, v.w);
        }
        uint4* dp = (uint4*)(A[0] + srow * LDH + sq * 16);
#pragma unroll
        for (int j = 0; j < 4; j++) dp[j] = ((uint4*)w)[j];
        if (tid < 32) ((int4*)idxb[0])[tid] = ((const int4*)(g_sdstD + e0))[tid];
        else if (tid < 64)
            ((int4*)(idxb[0] + 128))[tid - 32] = ((const int4*)(g_ssrcD + e0))[tid - 32];
    }
    __syncthreads();

    for (int t = 0; t < T; t++) {
        int cur = t & 1;
        bool more = (t + 1 < T);

        // prefetch next tile into registers (loads overlap the mma below)
        float pf[32];
        int4 pd4 = make_int4(0, 0, 0, 0), ps4 = make_int4(0, 0, 0, 0);
        if (more) {
            int e0 = (blockIdx.x + (size_t)(t + 1) * G) * 128;
            int edge = g_permD[e0 + sj];
            const float4* hp = (const float4*)(h + (size_t)edge * 128 + sq * 32);
#pragma unroll
            for (int i = 0; i < 8; i++) ((float4*)pf)[i] = hp[i];
            if (tid < 32) pd4 = ((const int4*)(g_sdstD + e0))[tid];
            else if (tid < 64) ps4 = ((const int4*)(g_ssrcD + e0))[tid - 32];
        }

        // fp16 mma: warp (wm,wn) -> rows wm*32..+31, cols wn*32..+31
        float acc[2][4][4] = {};
        {
            const uint32_t* ab = A[cur] + (wm * 32 + g) * LDH + tt;
            const uint32_t* bb = Bs + (wn * 32 + g) * LDH + tt;
#pragma unroll
            for (int ks = 0; ks < 8; ks++) {
                int k0 = ks * 8;
                uint32_t b[4][2];
#pragma unroll
                for (int nt = 0; nt < 4; nt++) {
                    b[nt][0] = bb[nt * 8 * LDH + k0];
                    b[nt][1] = bb[nt * 8 * LDH + k0 + 4];
                }
#pragma unroll
                for (int mt = 0; mt < 2; mt++) {
                    uint32_t a0 = ab[(mt * 16 + 0) * LDH + k0];
                    uint32_t a1 = ab[(mt * 16 + 8) * LDH + k0];
                    uint32_t a2 = ab[(mt * 16 + 0) * LDH + k0 + 4];
                    uint32_t a3 = ab[(mt * 16 + 8) * LDH + k0 + 4];
#pragma unroll
                    for (int nt = 0; nt < 4; nt++)
                        mma16h(acc[mt][nt], a0, a1, a2, a3, b[nt][0], b[nt][1]);
                }
            }
        }

        // this tile's indices (4 consecutive sorted edges per thread)
        int jb = wm * 32 + 4 * g;
        int4 dd = *(const int4*)(idxb[cur] + jb);
        int4 ss = *(const int4*)(idxb[cur] + 128 + jb);
        __syncthreads();  // everyone done reading A[cur]/idx[cur]

        // store prefetched tile into the other buffer
        if (more) {
            uint32_t w[16];
#pragma unroll
            for (int j = 0; j < 16; j++) w[j] = pk_f16x2(pf[2 * j], pf[2 * j + 1]);
            uint4* dp = (uint4*)(A[1 - cur] + srow * LDH + sq * 16);
#pragma unroll
            for (int j = 0; j < 4; j++) dp[j] = ((uint4*)w)[j];
            if (tid < 32) ((int4*)idxb[1 - cur])[tid] = pd4;
            else if (tid < 64) ((int4*)(idxb[1 - cur] + 128))[tid - 32] = ps4;
        }

        // epilogue: register segment-accumulation, red once per distinct dst
        int col0 = wn * 32 + tt * 4;
        int de[4] = {dd.x, dd.y, dd.z, dd.w};
        int se[4] = {ss.x, ss.y, ss.z, ss.w};
        int curd = de[0];
        const float* xaB = g_xab + (size_t)curd * 256 + col0;
        float4 A0 = *(const float4*)xaB;
        float4 A1 = *(const float4*)(xaB + 16);
        float4 ac0 = make_float4(0.f, 0.f, 0.f, 0.f);
        float4 ac1 = make_float4(0.f, 0.f, 0.f, 0.f);
#pragma unroll
        for (int c = 0; c < 4; c++) {
            int d = de[c];
            if (d != curd) {
                float* mp = g_mnode + (size_t)curd * 128 + col0;
                redv4(mp, ac0);
                redv4(mp + 16, ac1);
                curd = d;
                const float* xn = g_xab + (size_t)d * 256 + col0;
                A0 = *(const float4*)xn;
                A1 = *(const float4*)(xn + 16);
                ac0 = make_float4(0.f, 0.f, 0.f, 0.f);
                ac1 = make_float4(0.f, 0.f, 0.f, 0.f);
            }
            const float* xbB = g_xab + (size_t)se[c] * 256 + 128 + col0;
            float4 B0 = *(const float4*)xbB;
            float4 B1 = *(const float4*)(xbB + 16);
            int mt = c >> 1, i2 = (c & 1) * 2;
            ac0.x += fmaxf(acc[mt][0][i2] + A0.x + B0.x, 0.f);
            ac0.y += fmaxf(acc[mt][0][i2 + 1] + A0.y + B0.y, 0.f);
            ac0.z += fmaxf(acc[mt][1][i2] + A0.z + B0.z, 0.f);
            ac0.w += fmaxf(acc[mt][1][i2 + 1] + A0.w + B0.w, 0.f);
            ac1.x += fmaxf(acc[mt][2][i2] + A1.x + B1.x, 0.f);
            ac1.y += fmaxf(acc[mt][2][i2 + 1] + A1.y + B1.y, 0.f);
            ac1.z += fmaxf(acc[mt][3][i2] + A1.z + B1.z, 0.f);
            ac1.w += fmaxf(acc[mt][3][i2 + 1] + A1.w + B1.w, 0.f);
        }
        float* mp = g_mnode + (size_t)curd * 128 + col0;
        redv4(mp, ac0);
        redv4(mp + 16, ac1);
        __syncthreads();  // staged A/idx visible before next iteration's mma
    }
}

// ---------------- LN: warp per node over src-CSR ------------------------------
__global__ void __launch_bounds__(256) k_ln_node(const float* __restrict__ snorm,
                                                 const float* __restrict__ gamma,
                                                 const float* __restrict__ beta,
                                                 float* __restrict__ out) {
    int wid = threadIdx.x >> 5, lane = threadIdx.x & 31;
    int v = blockIdx.x * 8 + wid;
    int beg = g_startS[v], end = g_startS[v + 1];
    if (beg == end) return;

    float4 pv = ((const float4*)(g_p + (size_t)v * 128))[lane];
    float sum = pv.x + pv.y + pv.z + pv.w;
    float ssq = pv.x * pv.x + pv.y * pv.y + pv.z * pv.z + pv.w * pv.w;
#pragma unroll
    for (int o = 16; o > 0; o >>= 1) {
        sum += __shfl_xor_sync(0xffffffffu, sum, o);
        ssq += __shfl_xor_sync(0xffffffffu, ssq, o);
    }
    float mu = sum * 0.0078125f;
    float var = ssq * 0.0078125f - mu * mu;
    float4 gg = ((const float4*)gamma)[lane];
    float4 bb = ((const float4*)beta)[lane];
    float4 pm = make_float4(pv.x - mu, pv.y - mu, pv.z - mu, pv.w - mu);

    for (int q = beg; q < end; q++) {
        int e = g_permS[q];
        float s = snorm[e];
        float ts = s * rsqrtf(var * s * s + 1e-5f);
        float4 o4;
        o4.x = fmaxf(pm.x * ts * gg.x + bb.x, 0.f);
        o4.y = fmaxf(pm.y * ts * gg.y + bb.y, 0.f);
        o4.z = fmaxf(pm.z * ts * gg.z + bb.z, 0.f);
        o4.w = fmaxf(pm.w * ts * gg.w + bb.w, 0.f);
        ((float4*)(out + (size_t)e * 128))[lane] = o4;
    }
}

// ---------------------------------------------------------------------------
extern "C" void kernel_launch(void* const* d_in, const int* in_sizes, int n_in,
                              void* d_out, int out_size) {
    const float* x = (const float*)d_in[0];
    const float* h = (const float*)d_in[1];
    const float* snorm_n = (const float*)d_in[2];
    const float* W1 = (const float*)d_in[4];
    const float* W2 = (const float*)d_in[5];
    const float* gamma = (const float*)d_in[6];
    const float* beta = (const float*)d_in[7];
    const int* src = (const int*)d_in[8];
    const int* dst = (const int*)d_in[9];
    float* out = (float*)d_out;

    cudaFuncSetAttribute(k_xab_mma, cudaFuncAttributeMaxDynamicSharedMemorySize, XAB_SMEM);
    cudaFuncSetAttribute(k_p_mma, cudaFuncAttributeMaxDynamicSharedMemorySize, XAB_SMEM);
    cudaFuncSetAttribute(k_edge, cudaFuncAttributeMaxDynamicSharedMemorySize, EDGE_SMEM);

    void* mnode;
    void* histD;
    void* histS;
    cudaGetSymbolAddress(&mnode, g_mnode);
    cudaGetSymbolAddress(&histD, g_histD);
    cudaGetSymbolAddress(&histS, g_histS);

    cudaMemsetAsync(mnode, 0, (size_t)NN * 128 * 4);
    cudaMemsetAsync(histD, 0, NN * 4);
    cudaMemsetAsync(histS, 0, NN * 4);
    k_hist<<<2500, 256>>>(dst, src);
    k_scan_local<<<dim3(40, 2), 1024>>>();
    k_scan_bsum<<<1, 128>>>();
    k_scan_add<<<dim3(40, 2), 1024>>>();
    k_scatter<<<2500, 256>>>(dst, src);
    k_xab_mma<<<dim3(313, 2), 256, XAB_SMEM>>>(x, W1);
    k_edge<<<148, 512, EDGE_SMEM>>>(h, W1);
    k_p_mma<<<313, 256, XAB_SMEM>>>(W2);
    k_ln_node<<<5000, 256>>>(snorm_n, gamma, beta, out);
}